// round 2
// baseline (speedup 1.0000x reference)
#include <cuda_runtime.h>
#include <cstdint>

#define NS    16
#define NC    256
#define D     64
#define NPTS  32768
#define NBLK  (NPTS / 256)   // 128 assign blocks per space
#define NITER 5

// ---------------- scratch (no allocations allowed) ----------------
__device__ float          g_c[2][NS * NC * D];    // double-buffered centroids [s][k][d]
__device__ unsigned char  g_assign[NS * NPTS];    // per-point assignment
__device__ unsigned short g_bucket[NS * NPTS];    // point ids grouped (k-sorted, stable)
__device__ int            g_cnt[NS * NC];         // per-centroid counts
__device__ int            g_off[NS * NC];         // cross-k exclusive offsets
__device__ int            g_bh[NS * NBLK * NC];   // per-block histograms
__device__ int            g_bhoff[NS * NBLK * NC];// per-block intra-k exclusive prefix

// packed fp32x2 FMA (Blackwell; only reachable via PTX)
__device__ __forceinline__ unsigned long long fma2(unsigned long long a,
                                                   unsigned long long b,
                                                   unsigned long long c) {
    unsigned long long d;
    asm("fma.rn.f32x2 %0, %1, %2, %3;" : "=l"(d) : "l"(a), "l"(b), "l"(c));
    return d;
}

// ---------------- init: c0[s][k][d] = x[k][s][d] ----------------
__global__ void init_kernel(const float* __restrict__ x) {
    int gid = blockIdx.x * blockDim.x + threadIdx.x;   // 262144 total
    int d = gid & 63;
    int k = (gid >> 6) & 255;
    int s = gid >> 14;
    g_c[0][gid] = x[((size_t)k * NS + s) * D + d];
}

// ---------------- assign: argmin_k (|c|^2 - 2 x.c), per-block histogram ----------------
__global__ __launch_bounds__(256, 2)
void assign_kernel(const float* __restrict__ x, int cursel) {
    extern __shared__ float smem[];
    float* sc   = smem;                 // [256][64] centroids
    float* sc2  = smem + NC * D;        // [256] |c|^2
    int*   hist = (int*)(sc2 + NC);     // [256] block histogram

    const int s   = blockIdx.y;
    const int tid = threadIdx.x;

    hist[tid] = 0;

    // each thread loads centroid row k=tid, computes |c|^2 on the fly
    {
        const float* c = g_c[cursel] + ((size_t)s * NC + tid) * D;
        const float4* src = reinterpret_cast<const float4*>(c);
        float4* dst = reinterpret_cast<float4*>(sc + tid * D);
        float ss = 0.f;
#pragma unroll
        for (int i = 0; i < 16; i++) {
            float4 v = src[i];
            dst[i] = v;
            ss += v.x * v.x + v.y * v.y + v.z * v.z + v.w * v.w;
        }
        sc2[tid] = ss;
    }

    // each thread owns one point, kept packed as 32 f32x2 registers
    const int p = blockIdx.x * 256 + tid;
    unsigned long long xp[32];
    {
        const ulonglong2* xr =
            reinterpret_cast<const ulonglong2*>(x + ((size_t)p * NS + s) * D);
#pragma unroll
        for (int i = 0; i < 16; i++) {
            ulonglong2 v = xr[i];
            xp[2 * i]     = v.x;
            xp[2 * i + 1] = v.y;
        }
    }
    __syncthreads();

    float best = 3.4e38f;
    int   bidx = 0;

#pragma unroll 1
    for (int kb = 0; kb < NC; kb += 8) {
        unsigned long long acc[8];
#pragma unroll
        for (int j = 0; j < 8; j++) acc[j] = 0ULL;

#pragma unroll
        for (int dc = 0; dc < 16; dc++) {          // 4 dims per step
#pragma unroll
            for (int j = 0; j < 8; j++) {
                // broadcast load of c[kb+j][4dc..4dc+3] (same addr across warp)
                ulonglong2 cv = *reinterpret_cast<const ulonglong2*>(
                    sc + (kb + j) * D + dc * 4);
                acc[j] = fma2(xp[2 * dc],     cv.x, acc[j]);
                acc[j] = fma2(xp[2 * dc + 1], cv.y, acc[j]);
            }
        }

#pragma unroll
        for (int j = 0; j < 8; j++) {
            float lo, hi;
            asm("mov.b64 {%0,%1}, %2;" : "=f"(lo), "=f"(hi) : "l"(acc[j]));
            float dot  = lo + hi;
            float dist = __fmaf_rn(-2.f, dot, sc2[kb + j]);
            if (dist < best) { best = dist; bidx = kb + j; }   // first-min tiebreak
        }
    }

    g_assign[s * NPTS + p] = (unsigned char)bidx;
    atomicAdd(&hist[bidx], 1);      // smem atomic: count is order-independent
    __syncthreads();
    g_bh[((size_t)s * NBLK + blockIdx.x) * NC + tid] = hist[tid];
}

// ---------------- scan: per-k prefix over blocks + cross-k exclusive scan ----------------
__global__ void scan_kernel() {
    __shared__ int sm[NC];
    const int s = blockIdx.x, k = threadIdx.x;
    int run = 0;
#pragma unroll 4
    for (int b = 0; b < NBLK; b++) {
        int idx = ((size_t)s * NBLK + b) * NC + k;
        int v = g_bh[idx];
        g_bhoff[idx] = run;          // deterministic serial prefix
        run += v;
    }
    g_cnt[s * NC + k] = run;
    sm[k] = run;
    __syncthreads();
    for (int o = 1; o < NC; o <<= 1) {
        int add = (k >= o) ? sm[k - o] : 0;
        __syncthreads();
        sm[k] += add;
        __syncthreads();
    }
    g_off[s * NC + k] = sm[k] - run;
}

// ---------------- scatter: stable, atomic-free rank computation ----------------
__global__ void scatter_kernel() {
    __shared__ int warp_hist[8][NC];   // 8 KB
    const int s = blockIdx.y, b = blockIdx.x;
    const int tid = threadIdx.x, w = tid >> 5, lane = tid & 31;

    for (int i = tid; i < 8 * NC; i += 256)
        (&warp_hist[0][0])[i] = 0;
    __syncthreads();

    const int p = b * 256 + tid;
    const int a = g_assign[s * NPTS + p];

    unsigned mask = __match_any_sync(0xffffffffu, a);
    int lrank  = __popc(mask & ((1u << lane) - 1));
    int leader = __ffs(mask) - 1;
    if (lane == leader) warp_hist[w][a] = __popc(mask);
    __syncthreads();

    int pre = 0;
#pragma unroll
    for (int ww = 0; ww < 8; ww++)
        if (ww < w) pre += warp_hist[ww][a];

    int pos = g_off[s * NC + a]
            + g_bhoff[((size_t)s * NBLK + b) * NC + a]
            + pre + lrank;
    g_bucket[s * NPTS + pos] = (unsigned short)p;
}

// ---------------- update: mean of assigned points (fixed-order gather) ----------------
__global__ void update_kernel(const float* __restrict__ x, int cursel,
                              float* __restrict__ outp) {
    __shared__ unsigned short sl[256];
    const int s = blockIdx.y, k = blockIdx.x, t = threadIdx.x;  // t < 64 (dim)
    const int base  = s * NC + k;
    const int start = g_off[base];
    const int count = g_cnt[base];

    float acc0 = 0.f, acc1 = 0.f;
    for (int b = 0; b < count; b += 256) {
        int m = min(256, count - b);
        for (int j = t; j < m; j += 64)
            sl[j] = g_bucket[s * NPTS + start + b + j];
        __syncthreads();
        int i = 0;
        for (; i + 1 < m; i += 2) {
            int p0 = sl[i], p1 = sl[i + 1];
            acc0 += x[((size_t)p0 * NS + s) * D + t];
            acc1 += x[((size_t)p1 * NS + s) * D + t];
        }
        if (i < m) acc0 += x[((size_t)sl[i] * NS + s) * D + t];
        __syncthreads();
    }

    float sum = acc0 + acc1;
    float res = (count > 0) ? (sum / (float)count)
                            : g_c[cursel][(size_t)base * D + t];
    float* dst = outp ? outp : g_c[1 - cursel];
    dst[(size_t)base * D + t] = res;
}

// ---------------- launch ----------------
extern "C" void kernel_launch(void* const* d_in, const int* in_sizes, int n_in,
                              void* d_out, int out_size) {
    const float* x = (const float*)d_in[0];
    float* out = (float*)d_out;

    const size_t smem = (size_t)(NC * D + NC) * sizeof(float) + NC * sizeof(int);
    cudaFuncSetAttribute(assign_kernel,
                         cudaFuncAttributeMaxDynamicSharedMemorySize, (int)smem);

    init_kernel<<<(NS * NC * D) / 256, 256>>>(x);

    int cur = 0;
    for (int it = 0; it < NITER; ++it) {
        assign_kernel<<<dim3(NBLK, NS), 256, smem>>>(x, cur);
        scan_kernel<<<NS, NC>>>();
        scatter_kernel<<<dim3(NBLK, NS), 256>>>();
        update_kernel<<<dim3(NC, NS), 64>>>(x, cur,
                                            (it == NITER - 1) ? out : nullptr);
        cur ^= 1;
    }
}